// round 9
// baseline (speedup 1.0000x reference)
#include <cuda_runtime.h>
#include <cuda_bf16.h>
#include <cstdint>

// ============================================================================
// DigitConvolutionalModel: conv folds into W1 -> pure 4-layer MLP
//   784 -> 200 -> 200 -> 200 -> 10, batch 65536, fp32 in/out.
// bf16x3 split arithmetic, mma.sync.m16n8k16. CTA = 64 rows, 256 threads.
// Warp grid 2M x 4N, PERFECTLY BALANCED: each warp = 6 j-tiles x 2 m16 tiles
//   + exactly one extra (j,mtile) pair from the 2 leftover j-tiles
//   -> 39 MMAs per warp per k-chunk (was 42/36 unbalanced in prior round).
// h stored plane-major as MMA A-fragments (conflict-free STS/LDS).
// 3-deep cp.async ring, one __syncthreads per k-chunk. 2 CTAs/SM.
// ============================================================================

#define CTA_THREADS 256

#define NK1 49
#define NKH 13
#define NJH 26
#define NJO 2

// fragment-linear weights: uint4 per (ks, j, lane) = {b0h, b1h, b0l, b1l}
__device__ uint4 g_Wb1[NK1 * NJH * 32];
__device__ uint4 g_Wb2[NKH * NJH * 32];
__device__ uint4 g_Wb3[NKH * NJH * 32];
__device__ uint4 g_Wb4[NKH * NJO * 32];

// ---------------------------------------------------------------------------
__device__ __forceinline__ void split_pack(float x, float y, uint32_t& h, uint32_t& l) {
    __nv_bfloat16 hx = __float2bfloat16_rn(x);
    __nv_bfloat16 hy = __float2bfloat16_rn(y);
    float rx = x - __bfloat162float(hx);
    float ry = y - __bfloat162float(hy);
    __nv_bfloat162 H; H.x = hx; H.y = hy;
    __nv_bfloat162 L; L.x = __float2bfloat16_rn(rx); L.y = __float2bfloat16_rn(ry);
    h = *reinterpret_cast<uint32_t*>(&H);
    l = *reinterpret_cast<uint32_t*>(&L);
}

__device__ __forceinline__ void mma_bf16(float* c, const uint32_t* a,
                                         uint32_t b0, uint32_t b1) {
    asm volatile(
        "mma.sync.aligned.m16n8k16.row.col.f32.bf16.bf16.f32 "
        "{%0,%1,%2,%3},{%4,%5,%6,%7},{%8,%9},{%0,%1,%2,%3};"
        : "+f"(c[0]), "+f"(c[1]), "+f"(c[2]), "+f"(c[3])
        : "r"(a[0]), "r"(a[1]), "r"(a[2]), "r"(a[3]), "r"(b0), "r"(b1));
}

__device__ __forceinline__ void cp16(void* dst_smem, const void* src) {
    uint32_t d = (uint32_t)__cvta_generic_to_shared(dst_smem);
    asm volatile("cp.async.cg.shared.global [%0], [%1], 16;" :: "r"(d), "l"(src));
}
#define CP_COMMIT asm volatile("cp.async.commit_group;" ::: "memory")
#define CP_WAIT1  asm volatile("cp.async.wait_group 1;" ::: "memory")

// ---------------------------------------------------------------------------
// prep kernel (unchanged layout)
// ---------------------------------------------------------------------------
__device__ __forceinline__ float w_l1(const float* cw, const float* W1, int k, int n) {
    if (n >= 200) return 0.f;
    int r = k / 28, c = k % 28;
    float s = 0.f;
    #pragma unroll
    for (int dy = 0; dy < 3; ++dy) {
        int i = r - dy;
        if (i < 0 || i > 25) continue;
        #pragma unroll
        for (int dx = 0; dx < 3; ++dx) {
            int j = c - dx;
            if (j < 0 || j > 25) continue;
            s += cw[dy * 3 + dx] * W1[(i * 26 + j) * 200 + n];
        }
    }
    return s;
}

__global__ void prep_kernel(const float* __restrict__ cw,
                            const float* __restrict__ W1,
                            const float* __restrict__ W2,
                            const float* __restrict__ W3,
                            const float* __restrict__ W4) {
    int s = blockIdx.x * CTA_THREADS + threadIdx.x;
    const int E1 = NK1 * NJH * 32;
    const int E2 = E1 + NKH * NJH * 32;
    const int E3 = E2 + NKH * NJH * 32;
    const int E4 = E3 + NKH * NJO * 32;
    if (s >= E4) return;

    uint4* dst; int loc, nj, which;
    if (s < E1)      { dst = g_Wb1; loc = s;      nj = NJH; which = 1; }
    else if (s < E2) { dst = g_Wb2; loc = s - E1; nj = NJH; which = 2; }
    else if (s < E3) { dst = g_Wb3; loc = s - E2; nj = NJH; which = 3; }
    else             { dst = g_Wb4; loc = s - E3; nj = NJO; which = 4; }

    int lane = loc & 31;
    int j    = (loc >> 5) % nj;
    int ks   = loc / (nj * 32);
    int g = lane >> 2, t = lane & 3;
    int n  = 8 * j + g;
    int k0 = 16 * ks + 2 * t;

    float w0, w1, w8, w9;
    if (which == 1) {
        w0 = w_l1(cw, W1, k0,     n);
        w1 = w_l1(cw, W1, k0 + 1, n);
        w8 = w_l1(cw, W1, k0 + 8, n);
        w9 = w_l1(cw, W1, k0 + 9, n);
    } else if (which == 4) {
        w0 = (k0     < 200 && n < 10) ? W4[(k0)     * 10 + n] : 0.f;
        w1 = (k0 + 1 < 200 && n < 10) ? W4[(k0 + 1) * 10 + n] : 0.f;
        w8 = (k0 + 8 < 200 && n < 10) ? W4[(k0 + 8) * 10 + n] : 0.f;
        w9 = (k0 + 9 < 200 && n < 10) ? W4[(k0 + 9) * 10 + n] : 0.f;
    } else {
        const float* W = (which == 2) ? W2 : W3;
        w0 = (k0     < 200 && n < 200) ? W[(k0)     * 200 + n] : 0.f;
        w1 = (k0 + 1 < 200 && n < 200) ? W[(k0 + 1) * 200 + n] : 0.f;
        w8 = (k0 + 8 < 200 && n < 200) ? W[(k0 + 8) * 200 + n] : 0.f;
        w9 = (k0 + 9 < 200 && n < 200) ? W[(k0 + 9) * 200 + n] : 0.f;
    }

    uint32_t b0h, b0l, b1h, b1l;
    split_pack(w0, w1, b0h, b0l);
    split_pack(w8, w9, b1h, b1l);
    dst[loc] = make_uint4(b0h, b1h, b0l, b1l);
}

// ---------------------------------------------------------------------------
// main fused kernel
// SMEM (floats):
//   [0,3840)        xs: 3 x [64][20] fp32 x-stage (stride 20)
//   [3840,13824)    ws: 3 x [832] uint4 weight stage
//   [13824,20480)   hfh: [13][4][4][32] u32  A-fragments hi (26624 B)
//   [20480,27136)   hfl: same, lo
//   [27136,27776)   sb: biases
// ---------------------------------------------------------------------------
#define SMEM_BYTES 111104

__global__ void __launch_bounds__(CTA_THREADS, 2)
mlp_kernel(const float* __restrict__ x,
           const float* __restrict__ b1, const float* __restrict__ b2,
           const float* __restrict__ b3, const float* __restrict__ b4,
           float* __restrict__ out) {
    extern __shared__ float smf[];
    float*    xs  = smf;                               // 3 x 1280 floats
    uint4*    ws  = (uint4*)(smf + 3840);              // 3 x 832 uint4
    uint32_t* hfh = (uint32_t*)(smf + 13824);          // 13*4*4*32 u32
    uint32_t* hfl = (uint32_t*)(smf + 20480);
    float*    sb  = smf + 27136;

    const int tid  = threadIdx.x;
    const int lane = tid & 31;
    const int warp = tid >> 5;
    const int g = lane >> 2, t = lane & 3;
    const int mh  = warp >> 2;                 // M-half: rows mh*32..mh*32+31
    const int nq  = warp & 3;                  // N-quarter
    const int jb  = 6 * nq;                    // main j-tiles [jb, jb+6)
    const int je  = 24 + (nq & 1);             // extra j-tile (24 or 25)
    const int emt = nq >> 1;                   // extra pair: mt index in-half
    const int r0  = blockIdx.x * 64;

    if (tid < 208) {
        sb[tid]       = (tid < 200) ? b1[tid] : 0.f;
        sb[208 + tid] = (tid < 200) ? b2[tid] : 0.f;
        sb[416 + tid] = (tid < 200) ? b3[tid] : 0.f;
    }
    if (tid < 16) sb[624 + tid] = (tid < 10) ? b4[tid] : 0.f;

    float C[2][6][4];     // main: 2 m16 tiles x 6 j-tiles
    float CE[4];          // extra pair (je, 2mh+emt)

    // --------------------- helpers ---------------------
    auto stage_w = [&](const uint4* src, int count, int buf) {
        uint4* d = ws + buf * 832;
        for (int i = tid; i < count; i += CTA_THREADS) cp16(d + i, src + i);
    };
    auto stage_x = [&](int ks, int buf) {
        float* d = xs + buf * 1280;
        int row = tid >> 2, seg = tid & 3;
        cp16(d + row * 20 + seg * 4, x + (size_t)(r0 + row) * 784 + ks * 16 + seg * 4);
    };
    auto zeroC = [&]() {
        #pragma unroll
        for (int mt = 0; mt < 2; ++mt)
            #pragma unroll
            for (int j = 0; j < 6; ++j)
                #pragma unroll
                for (int q = 0; q < 4; ++q) C[mt][j][q] = 0.f;
        #pragma unroll
        for (int q = 0; q < 4; ++q) CE[q] = 0.f;
    };
    // store one (J, mtile) C-quad into plane-major fragment layout
    auto put_pair = [&](int J, int mtile, const float* c, const float* bias) {
        float2 bb = *(const float2*)(bias + 8 * J + 2 * t);
        float v0 = fmaxf(c[0] + bb.x, 0.f);
        float v1 = fmaxf(c[1] + bb.y, 0.f);
        float v2 = fmaxf(c[2] + bb.x, 0.f);
        float v3 = fmaxf(c[3] + bb.y, 0.f);
        uint32_t H0, L0, H1, L1;
        split_pack(v0, v1, H0, L0);
        split_pack(v2, v3, H1, L1);
        int ks = J >> 1, kb = J & 1;
        int idx = (((ks * 4 + mtile) * 4) + 2 * kb) * 32 + lane;
        hfh[idx]      = H0;  hfl[idx]      = L0;
        hfh[idx + 32] = H1;  hfl[idx + 32] = L1;
    };
    auto store_h = [&](const float* bias) {
        #pragma unroll
        for (int mt = 0; mt < 2; ++mt)
            #pragma unroll
            for (int j = 0; j < 6; ++j)
                put_pair(jb + j, mh * 2 + mt, C[mt][j], bias);
        put_pair(je, mh * 2 + emt, CE, bias);
    };
    // consumer: direct A-fragment loads, conflict-free LDS.32
    auto load_a_h = [&](int ks, uint32_t ah[2][4], uint32_t al[2][4]) {
        #pragma unroll
        for (int mt = 0; mt < 2; ++mt) {
            int base = ((ks * 4 + (mh * 2 + mt)) * 4) * 32 + lane;
            #pragma unroll
            for (int r = 0; r < 4; ++r) {
                ah[mt][r] = hfh[base + 32 * r];
                al[mt][r] = hfl[base + 32 * r];
            }
        }
    };
    // 39 MMAs, identical on every warp
    auto mma_train = [&](const uint4* wt, const uint32_t ah[2][4], const uint32_t al[2][4]) {
        #pragma unroll
        for (int j = 0; j < 6; ++j) {
            uint4 w = wt[(jb + j) * 32];
            #pragma unroll
            for (int mt = 0; mt < 2; ++mt) {
                mma_bf16(C[mt][j], ah[mt], w.x, w.y);   // hi*hi
                mma_bf16(C[mt][j], al[mt], w.x, w.y);   // lo*hi
                mma_bf16(C[mt][j], ah[mt], w.z, w.w);   // hi*lo
            }
        }
        uint4 w = wt[je * 32];
        mma_bf16(CE, ah[emt], w.x, w.y);
        mma_bf16(CE, al[emt], w.x, w.y);
        mma_bf16(CE, ah[emt], w.z, w.w);
    };

    // =========================== Layer 1 (K=784) ===========================
    zeroC();
    stage_x(0, 0); stage_w(g_Wb1, 832, 0); CP_COMMIT;
    stage_x(1, 1); stage_w(g_Wb1 + 832, 832, 1); CP_COMMIT;
    {
        int cur = 0, st = 2;
        for (int ks = 0; ks < NK1; ++ks) {
            CP_WAIT1;
            __syncthreads();
            if (ks + 2 < NK1) { stage_x(ks + 2, st); stage_w(g_Wb1 + (ks + 2) * 832, 832, st); }
            CP_COMMIT;

            uint32_t ah[2][4], al[2][4];
            #pragma unroll
            for (int mt = 0; mt < 2; ++mt) {
                const float* xb = xs + cur * 1280 + (mh * 32 + mt * 16 + g) * 20;
                float2 p0 = *(const float2*)(xb + 2 * t);
                float2 p1 = *(const float2*)(xb + 160 + 2 * t);        // row+8
                float2 p2 = *(const float2*)(xb + 2 * t + 8);          // k+8
                float2 p3 = *(const float2*)(xb + 160 + 2 * t + 8);
                split_pack(p0.x, p0.y, ah[mt][0], al[mt][0]);
                split_pack(p1.x, p1.y, ah[mt][1], al[mt][1]);
                split_pack(p2.x, p2.y, ah[mt][2], al[mt][2]);
                split_pack(p3.x, p3.y, ah[mt][3], al[mt][3]);
            }
            mma_train(ws + cur * 832 + lane, ah, al);
            if (++cur == 3) cur = 0;
            if (++st  == 3) st  = 0;
        }
    }
    __syncthreads();
    store_h(sb);
    __syncthreads();

    // ======================= Layers 2 & 3 (K=208) ==========================
    const uint4* Wmid[2] = { g_Wb2, g_Wb3 };
    for (int l = 0; l < 2; ++l) {
        zeroC();
        stage_w(Wmid[l], 832, 0); CP_COMMIT;
        stage_w(Wmid[l] + 832, 832, 1); CP_COMMIT;
        int cur = 0, st = 2;
        for (int ks = 0; ks < NKH; ++ks) {
            CP_WAIT1;
            __syncthreads();
            if (ks + 2 < NKH) stage_w(Wmid[l] + (ks + 2) * 832, 832, st);
            CP_COMMIT;

            uint32_t ah[2][4], al[2][4];
            load_a_h(ks, ah, al);
            mma_train(ws + cur * 832 + lane, ah, al);
            if (++cur == 3) cur = 0;
            if (++st  == 3) st  = 0;
        }
        __syncthreads();
        store_h(sb + 208 * (l + 1));
        __syncthreads();
    }

    // =========================== Layer 4 (N=10) ============================
    // 2 n8-tiles x 4 m16-tiles = 8 (j,mtile) pairs -> exactly one per warp.
    float C4[4];
    #pragma unroll
    for (int q = 0; q < 4; ++q) C4[q] = 0.f;
    const int j4 = nq & 1;                 // n8 tile
    // warp's m16 tile for layer 4 = 2mh + emt (within its own m-half)

    stage_w(g_Wb4, 64, 0); CP_COMMIT;
    stage_w(g_Wb4 + 64, 64, 1); CP_COMMIT;
    {
        int cur = 0, st = 2;
        for (int ks = 0; ks < NKH; ++ks) {
            CP_WAIT1;
            __syncthreads();
            if (ks + 2 < NKH) stage_w(g_Wb4 + (ks + 2) * 64, 64, st);
            CP_COMMIT;

            uint32_t ah[4], al[4];
            {
                int base = ((ks * 4 + (mh * 2 + emt)) * 4) * 32 + lane;
                #pragma unroll
                for (int r = 0; r < 4; ++r) {
                    ah[r] = hfh[base + 32 * r];
                    al[r] = hfl[base + 32 * r];
                }
            }
            uint4 w = ws[cur * 832 + j4 * 32 + lane];
            mma_bf16(C4, ah, w.x, w.y);
            mma_bf16(C4, al, w.x, w.y);
            mma_bf16(C4, ah, w.z, w.w);
            if (++cur == 3) cur = 0;
            if (++st  == 3) st  = 0;
        }
    }

    // output: warp covers m16 tile (2mh+emt), n8 tile j4; cols 8*j4+2t..+1
    {
        int col = 8 * j4 + 2 * t;
        if (col < 10) {
            float2 bb = *(const float2*)(sb + 624 + col);
            int rowg = r0 + mh * 32 + emt * 16 + g;
            float2 o0 = { C4[0] + bb.x, C4[1] + bb.y };
            float2 o1 = { C4[2] + bb.x, C4[3] + bb.y };
            *(float2*)(out + (size_t)rowg * 10 + col)       = o0;
            *(float2*)(out + (size_t)(rowg + 8) * 10 + col) = o1;
        }
    }
}

// ---------------------------------------------------------------------------
extern "C" void kernel_launch(void* const* d_in, const int* in_sizes, int n_in,
                              void* d_out, int out_size) {
    const float* x  = (const float*)d_in[0];
    const float* cw = (const float*)d_in[1];
    const float* W1 = (const float*)d_in[2];
    const float* b1 = (const float*)d_in[3];
    const float* W2 = (const float*)d_in[4];
    const float* b2 = (const float*)d_in[5];
    const float* W3 = (const float*)d_in[6];
    const float* b3 = (const float*)d_in[7];
    const float* W4 = (const float*)d_in[8];
    const float* b4 = (const float*)d_in[9];
    float* out = (float*)d_out;

    cudaFuncSetAttribute(mlp_kernel, cudaFuncAttributeMaxDynamicSharedMemorySize, SMEM_BYTES);

    prep_kernel<<<247, CTA_THREADS>>>(cw, W1, W2, W3, W4);
    mlp_kernel<<<1024, CTA_THREADS, SMEM_BYTES>>>(x, b1, b2, b3, b4, out);
}

// round 10
// speedup vs baseline: 1.0023x; 1.0023x over previous
#include <cuda_runtime.h>
#include <cuda_bf16.h>
#include <cstdint>

// ============================================================================
// DigitConvolutionalModel: conv folds into W1 -> pure 4-layer MLP
//   784 -> 200 -> 200 -> 200 -> 10, batch 65536, fp32 in/out.
// bf16x3 split arithmetic, mma.sync.m16n8k16. CTA = 64 rows, 256 threads,
// 8 warps = 4 M-quarters(16 rows) x 2 N-halves, 13 j-tiles per warp (balanced).
// KEY CHANGE vs best (R7): W fragments are loaded DIRECTLY from GMEM via
// __ldg (coalesced LDG.128, L2/L1-hot) -- no SMEM weight ring, no W LDS,
// and layers 2/3/4 have ZERO barriers inside their k-loops.
// Layer 1 keeps a small 3-slot cp.async ring for x only (1 barrier/chunk).
// SMEM 73.2 KB -> 2 CTAs/SM (reg-limited).
// ============================================================================

#define CTA_THREADS 256

#define NK1 49
#define NKH 13
#define NJH 26
#define NJO 2

// fragment-linear weights: uint4 per (ks, j, lane) = {b0h, b1h, b0l, b1l}
__device__ uint4 g_Wb1[NK1 * NJH * 32];
__device__ uint4 g_Wb2[NKH * NJH * 32];
__device__ uint4 g_Wb3[NKH * NJH * 32];
__device__ uint4 g_Wb4[NKH * NJO * 32];

// ---------------------------------------------------------------------------
__device__ __forceinline__ void split_pack(float x, float y, uint32_t& h, uint32_t& l) {
    __nv_bfloat16 hx = __float2bfloat16_rn(x);
    __nv_bfloat16 hy = __float2bfloat16_rn(y);
    float rx = x - __bfloat162float(hx);
    float ry = y - __bfloat162float(hy);
    __nv_bfloat162 H; H.x = hx; H.y = hy;
    __nv_bfloat162 L; L.x = __float2bfloat16_rn(rx); L.y = __float2bfloat16_rn(ry);
    h = *reinterpret_cast<uint32_t*>(&H);
    l = *reinterpret_cast<uint32_t*>(&L);
}

__device__ __forceinline__ void mma_bf16(float* c, const uint32_t* a,
                                         uint32_t b0, uint32_t b1) {
    asm volatile(
        "mma.sync.aligned.m16n8k16.row.col.f32.bf16.bf16.f32 "
        "{%0,%1,%2,%3},{%4,%5,%6,%7},{%8,%9},{%0,%1,%2,%3};"
        : "+f"(c[0]), "+f"(c[1]), "+f"(c[2]), "+f"(c[3])
        : "r"(a[0]), "r"(a[1]), "r"(a[2]), "r"(a[3]), "r"(b0), "r"(b1));
}

__device__ __forceinline__ void cp16(void* dst_smem, const void* src) {
    uint32_t d = (uint32_t)__cvta_generic_to_shared(dst_smem);
    asm volatile("cp.async.cg.shared.global [%0], [%1], 16;" :: "r"(d), "l"(src));
}
#define CP_COMMIT asm volatile("cp.async.commit_group;" ::: "memory")
#define CP_WAIT1  asm volatile("cp.async.wait_group 1;" ::: "memory")

// ---------------------------------------------------------------------------
// prep kernel: fold conv into W1eff, bf16 hi/lo split, fragment-linearize
// ---------------------------------------------------------------------------
__device__ __forceinline__ float w_l1(const float* cw, const float* W1, int k, int n) {
    if (n >= 200) return 0.f;
    int r = k / 28, c = k % 28;
    float s = 0.f;
    #pragma unroll
    for (int dy = 0; dy < 3; ++dy) {
        int i = r - dy;
        if (i < 0 || i > 25) continue;
        #pragma unroll
        for (int dx = 0; dx < 3; ++dx) {
            int j = c - dx;
            if (j < 0 || j > 25) continue;
            s += cw[dy * 3 + dx] * W1[(i * 26 + j) * 200 + n];
        }
    }
    return s;
}

__global__ void prep_kernel(const float* __restrict__ cw,
                            const float* __restrict__ W1,
                            const float* __restrict__ W2,
                            const float* __restrict__ W3,
                            const float* __restrict__ W4) {
    int s = blockIdx.x * CTA_THREADS + threadIdx.x;
    const int E1 = NK1 * NJH * 32;
    const int E2 = E1 + NKH * NJH * 32;
    const int E3 = E2 + NKH * NJH * 32;
    const int E4 = E3 + NKH * NJO * 32;
    if (s >= E4) return;

    uint4* dst; int loc, nj, which;
    if (s < E1)      { dst = g_Wb1; loc = s;      nj = NJH; which = 1; }
    else if (s < E2) { dst = g_Wb2; loc = s - E1; nj = NJH; which = 2; }
    else if (s < E3) { dst = g_Wb3; loc = s - E2; nj = NJH; which = 3; }
    else             { dst = g_Wb4; loc = s - E3; nj = NJO; which = 4; }

    int lane = loc & 31;
    int j    = (loc >> 5) % nj;
    int ks   = loc / (nj * 32);
    int g = lane >> 2, t = lane & 3;
    int n  = 8 * j + g;
    int k0 = 16 * ks + 2 * t;

    float w0, w1, w8, w9;
    if (which == 1) {
        w0 = w_l1(cw, W1, k0,     n);
        w1 = w_l1(cw, W1, k0 + 1, n);
        w8 = w_l1(cw, W1, k0 + 8, n);
        w9 = w_l1(cw, W1, k0 + 9, n);
    } else if (which == 4) {
        w0 = (k0     < 200 && n < 10) ? W4[(k0)     * 10 + n] : 0.f;
        w1 = (k0 + 1 < 200 && n < 10) ? W4[(k0 + 1) * 10 + n] : 0.f;
        w8 = (k0 + 8 < 200 && n < 10) ? W4[(k0 + 8) * 10 + n] : 0.f;
        w9 = (k0 + 9 < 200 && n < 10) ? W4[(k0 + 9) * 10 + n] : 0.f;
    } else {
        const float* W = (which == 2) ? W2 : W3;
        w0 = (k0     < 200 && n < 200) ? W[(k0)     * 200 + n] : 0.f;
        w1 = (k0 + 1 < 200 && n < 200) ? W[(k0 + 1) * 200 + n] : 0.f;
        w8 = (k0 + 8 < 200 && n < 200) ? W[(k0 + 8) * 200 + n] : 0.f;
        w9 = (k0 + 9 < 200 && n < 200) ? W[(k0 + 9) * 200 + n] : 0.f;
    }

    uint32_t b0h, b0l, b1h, b1l;
    split_pack(w0, w1, b0h, b0l);
    split_pack(w8, w9, b1h, b1l);
    dst[loc] = make_uint4(b0h, b1h, b0l, b1l);
}

// ---------------------------------------------------------------------------
// main fused kernel (M = 64 rows per CTA, W direct from GMEM)
// SMEM (floats):
//   [0,3840)        xs: 3 x [64][20] fp32 x-stage (stride 20)
//   [3840,10752)    h_hi: [64][216] bf16 (as 64*108 u32, stride 108 u32)
//   [10752,17664)   h_lo: same
//   [17664,18304)   sb: biases b1[208] b2[208] b3[208] b4[16]
// ---------------------------------------------------------------------------
#define SMEM_BYTES 73216

__global__ void __launch_bounds__(CTA_THREADS, 2)
mlp_kernel(const float* __restrict__ x,
           const float* __restrict__ b1, const float* __restrict__ b2,
           const float* __restrict__ b3, const float* __restrict__ b4,
           float* __restrict__ out) {
    extern __shared__ float smf[];
    float*    xs = smf;                               // 3 x 1280 floats
    uint32_t* hh = (uint32_t*)(smf + 3840);           // 64*108 u32
    uint32_t* hl = (uint32_t*)(smf + 10752);
    float*    sb = smf + 17664;

    const int tid  = threadIdx.x;
    const int lane = tid & 31;
    const int warp = tid >> 5;
    const int g = lane >> 2, t = lane & 3;
    const int mq = warp >> 1;       // M-quarter 0..3 (16 rows each)
    const int nh = warp & 1;        // N-half
    const int r0 = blockIdx.x * 64;

    // biases (padded)
    if (tid < 208) {
        sb[tid]       = (tid < 200) ? b1[tid] : 0.f;
        sb[208 + tid] = (tid < 200) ? b2[tid] : 0.f;
        sb[416 + tid] = (tid < 200) ? b3[tid] : 0.f;
    }
    if (tid < 16) sb[624 + tid] = (tid < 10) ? b4[tid] : 0.f;

    float C[13][4];

    // --------------------- helpers ---------------------
    auto stage_x = [&](int ks, int buf) {
        float* d = xs + buf * 1280;
        int row = tid >> 2, seg = tid & 3;
        cp16(d + row * 20 + seg * 4, x + (size_t)(r0 + row) * 784 + ks * 16 + seg * 4);
    };
    auto zeroC = [&]() {
        #pragma unroll
        for (int j = 0; j < 13; ++j)
            #pragma unroll
            for (int q = 0; q < 4; ++q) C[j][q] = 0.f;
    };
    auto store_h = [&](const float* bias) {
        int row = mq * 16 + g;
        #pragma unroll
        for (int j = 0; j < 13; ++j) {
            int J = 13 * nh + j;
            float2 bb = *(const float2*)(bias + 8 * J + 2 * t);
            float v0 = fmaxf(C[j][0] + bb.x, 0.f);
            float v1 = fmaxf(C[j][1] + bb.y, 0.f);
            float v2 = fmaxf(C[j][2] + bb.x, 0.f);
            float v3 = fmaxf(C[j][3] + bb.y, 0.f);
            uint32_t H, L;
            split_pack(v0, v1, H, L);
            hh[row * 108 + 4 * J + t] = H;
            hl[row * 108 + 4 * J + t] = L;
            split_pack(v2, v3, H, L);
            hh[(row + 8) * 108 + 4 * J + t] = H;
            hl[(row + 8) * 108 + 4 * J + t] = L;
        }
    };
    auto load_a_h = [&](int ks, uint32_t ah[4], uint32_t al[4]) {
        int base = (mq * 16 + g) * 108 + 8 * ks + t;
        ah[0] = hh[base];
        ah[1] = hh[base + 8 * 108];
        ah[2] = hh[base + 4];
        ah[3] = hh[base + 4 + 8 * 108];
        al[0] = hl[base];
        al[1] = hl[base + 8 * 108];
        al[2] = hl[base + 4];
        al[3] = hl[base + 4 + 8 * 108];
    };
    // 39 MMAs per warp; W straight from GMEM (L2/L1-hot, coalesced LDG.128)
    auto mma_train = [&](const uint4* __restrict__ wg,
                         const uint32_t ah[4], const uint32_t al[4]) {
        #pragma unroll
        for (int j = 0; j < 13; ++j) {
            uint4 w = __ldg(wg + j * 32);
            mma_bf16(C[j], ah, w.x, w.y);   // hi*hi
            mma_bf16(C[j], al, w.x, w.y);   // lo*hi
            mma_bf16(C[j], ah, w.z, w.w);   // hi*lo
        }
    };

    // =========================== Layer 1 (K=784) ===========================
    zeroC();
    stage_x(0, 0); CP_COMMIT;
    stage_x(1, 1); CP_COMMIT;
    {
        int cur = 0, st = 2;
        for (int ks = 0; ks < NK1; ++ks) {
            CP_WAIT1;                      // x group ks complete
            __syncthreads();               // visibility + WAR for buf st
            if (ks + 2 < NK1) stage_x(ks + 2, st);
            CP_COMMIT;

            uint32_t ah[4], al[4];
            {
                const float* xb = xs + cur * 1280 + (mq * 16 + g) * 20;
                float2 p0 = *(const float2*)(xb + 2 * t);
                float2 p1 = *(const float2*)(xb + 160 + 2 * t);        // row+8
                float2 p2 = *(const float2*)(xb + 2 * t + 8);          // k+8
                float2 p3 = *(const float2*)(xb + 160 + 2 * t + 8);
                split_pack(p0.x, p0.y, ah[0], al[0]);
                split_pack(p1.x, p1.y, ah[1], al[1]);
                split_pack(p2.x, p2.y, ah[2], al[2]);
                split_pack(p3.x, p3.y, ah[3], al[3]);
            }
            mma_train(g_Wb1 + ks * 832 + nh * 13 * 32 + lane, ah, al);
            if (++cur == 3) cur = 0;
            if (++st  == 3) st  = 0;
        }
    }
    __syncthreads();
    store_h(sb);
    __syncthreads();

    // ======================= Layers 2 & 3 (K=208) ==========================
    // h is stable for the whole layer -> NO barriers inside the k-loop.
    const uint4* Wmid[2] = { g_Wb2, g_Wb3 };
    for (int l = 0; l < 2; ++l) {
        zeroC();
        for (int ks = 0; ks < NKH; ++ks) {
            uint32_t ah[4], al[4];
            load_a_h(ks, ah, al);
            mma_train(Wmid[l] + ks * 832 + nh * 13 * 32 + lane, ah, al);
        }
        __syncthreads();                 // all h reads done before overwrite
        store_h(sb + 208 * (l + 1));
        __syncthreads();
    }

    // =========================== Layer 4 (N=10) ============================
    float C4[4];
    #pragma unroll
    for (int q = 0; q < 4; ++q) C4[q] = 0.f;

    for (int ks = 0; ks < NKH; ++ks) {
        uint32_t ah[4], al[4];
        load_a_h(ks, ah, al);
        uint4 w = __ldg(g_Wb4 + ks * 64 + nh * 32 + lane);
        mma_bf16(C4, ah, w.x, w.y);
        mma_bf16(C4, al, w.x, w.y);
        mma_bf16(C4, ah, w.z, w.w);
    }

    // output: cols 0..9 (tile nh*8 + 2t; guard padded cols)
    if (nh == 0 || t == 0) {
        int col = 8 * nh + 2 * t;
        float2 bb = *(const float2*)(sb + 624 + col);
        int rowg = r0 + mq * 16 + g;
        float2 o0 = { C4[0] + bb.x, C4[1] + bb.y };
        float2 o1 = { C4[2] + bb.x, C4[3] + bb.y };
        *(float2*)(out + (size_t)rowg * 10 + col)       = o0;
        *(float2*)(out + (size_t)(rowg + 8) * 10 + col) = o1;
    }
}

// ---------------------------------------------------------------------------
extern "C" void kernel_launch(void* const* d_in, const int* in_sizes, int n_in,
                              void* d_out, int out_size) {
    const float* x  = (const float*)d_in[0];
    const float* cw = (const float*)d_in[1];
    const float* W1 = (const float*)d_in[2];
    const float* b1 = (const float*)d_in[3];
    const float* W2 = (const float*)d_in[4];
    const float* b2 = (const float*)d_in[5];
    const float* W3 = (const float*)d_in[6];
    const float* b3 = (const float*)d_in[7];
    const float* W4 = (const float*)d_in[8];
    const float* b4 = (const float*)d_in[9];
    float* out = (float*)d_out;

    cudaFuncSetAttribute(mlp_kernel, cudaFuncAttributeMaxDynamicSharedMemorySize, SMEM_BYTES);

    prep_kernel<<<247, CTA_THREADS>>>(cw, W1, W2, W3, W4);
    mlp_kernel<<<1024, CTA_THREADS, SMEM_BYTES>>>(x, b1, b2, b3, b4, out);
}

// round 11
// speedup vs baseline: 1.1648x; 1.1621x over previous
#include <cuda_runtime.h>
#include <cuda_bf16.h>
#include <cstdint>

// ============================================================================
// DigitConvolutionalModel: conv folds into W1 -> pure 4-layer MLP
//   784 -> 200 -> 200 -> 200 -> 10, batch 65536, fp32 in/out.
// bf16x3 split arithmetic, mma.sync.m16n8k16. CTA = 64 rows, 256 threads,
// 8 warps = 4 M-quarters(16 rows) x 2 N-halves, 13 j-tiles/warp (balanced).
// 3-deep cp.async ring, one __syncthreads per k-chunk, 2 CTAs/SM.  (== R7)
// THIS ROUND: MMA issue order interleaved by j-groups {5,4,4}: term-major
// within a group -> RAW distance between dependent HMMAs rises 1 -> 4..5,
// covering HMMA latency that previously pinned tensor pipe at ~56%.
// ============================================================================

#define CTA_THREADS 256

#define NK1 49
#define NKH 13
#define NJH 26
#define NJO 2

// fragment-linear weights: uint4 per (ks, j, lane) = {b0h, b1h, b0l, b1l}
__device__ uint4 g_Wb1[NK1 * NJH * 32];
__device__ uint4 g_Wb2[NKH * NJH * 32];
__device__ uint4 g_Wb3[NKH * NJH * 32];
__device__ uint4 g_Wb4[NKH * NJO * 32];

// ---------------------------------------------------------------------------
__device__ __forceinline__ void split_pack(float x, float y, uint32_t& h, uint32_t& l) {
    __nv_bfloat16 hx = __float2bfloat16_rn(x);
    __nv_bfloat16 hy = __float2bfloat16_rn(y);
    float rx = x - __bfloat162float(hx);
    float ry = y - __bfloat162float(hy);
    __nv_bfloat162 H; H.x = hx; H.y = hy;
    __nv_bfloat162 L; L.x = __float2bfloat16_rn(rx); L.y = __float2bfloat16_rn(ry);
    h = *reinterpret_cast<uint32_t*>(&H);
    l = *reinterpret_cast<uint32_t*>(&L);
}

__device__ __forceinline__ void mma_bf16(float* c, const uint32_t* a,
                                         uint32_t b0, uint32_t b1) {
    asm volatile(
        "mma.sync.aligned.m16n8k16.row.col.f32.bf16.bf16.f32 "
        "{%0,%1,%2,%3},{%4,%5,%6,%7},{%8,%9},{%0,%1,%2,%3};"
        : "+f"(c[0]), "+f"(c[1]), "+f"(c[2]), "+f"(c[3])
        : "r"(a[0]), "r"(a[1]), "r"(a[2]), "r"(a[3]), "r"(b0), "r"(b1));
}

__device__ __forceinline__ void cp16(void* dst_smem, const void* src) {
    uint32_t d = (uint32_t)__cvta_generic_to_shared(dst_smem);
    asm volatile("cp.async.cg.shared.global [%0], [%1], 16;" :: "r"(d), "l"(src));
}
#define CP_COMMIT asm volatile("cp.async.commit_group;" ::: "memory")
#define CP_WAIT1  asm volatile("cp.async.wait_group 1;" ::: "memory")

// ---------------------------------------------------------------------------
// prep kernel: fold conv into W1eff, bf16 hi/lo split, fragment-linearize
// ---------------------------------------------------------------------------
__device__ __forceinline__ float w_l1(const float* cw, const float* W1, int k, int n) {
    if (n >= 200) return 0.f;
    int r = k / 28, c = k % 28;
    float s = 0.f;
    #pragma unroll
    for (int dy = 0; dy < 3; ++dy) {
        int i = r - dy;
        if (i < 0 || i > 25) continue;
        #pragma unroll
        for (int dx = 0; dx < 3; ++dx) {
            int j = c - dx;
            if (j < 0 || j > 25) continue;
            s += cw[dy * 3 + dx] * W1[(i * 26 + j) * 200 + n];
        }
    }
    return s;
}

__global__ void prep_kernel(const float* __restrict__ cw,
                            const float* __restrict__ W1,
                            const float* __restrict__ W2,
                            const float* __restrict__ W3,
                            const float* __restrict__ W4) {
    int s = blockIdx.x * CTA_THREADS + threadIdx.x;
    const int E1 = NK1 * NJH * 32;
    const int E2 = E1 + NKH * NJH * 32;
    const int E3 = E2 + NKH * NJH * 32;
    const int E4 = E3 + NKH * NJO * 32;
    if (s >= E4) return;

    uint4* dst; int loc, nj, which;
    if (s < E1)      { dst = g_Wb1; loc = s;      nj = NJH; which = 1; }
    else if (s < E2) { dst = g_Wb2; loc = s - E1; nj = NJH; which = 2; }
    else if (s < E3) { dst = g_Wb3; loc = s - E2; nj = NJH; which = 3; }
    else             { dst = g_Wb4; loc = s - E3; nj = NJO; which = 4; }

    int lane = loc & 31;
    int j    = (loc >> 5) % nj;
    int ks   = loc / (nj * 32);
    int g = lane >> 2, t = lane & 3;
    int n  = 8 * j + g;
    int k0 = 16 * ks + 2 * t;

    float w0, w1, w8, w9;
    if (which == 1) {
        w0 = w_l1(cw, W1, k0,     n);
        w1 = w_l1(cw, W1, k0 + 1, n);
        w8 = w_l1(cw, W1, k0 + 8, n);
        w9 = w_l1(cw, W1, k0 + 9, n);
    } else if (which == 4) {
        w0 = (k0     < 200 && n < 10) ? W4[(k0)     * 10 + n] : 0.f;
        w1 = (k0 + 1 < 200 && n < 10) ? W4[(k0 + 1) * 10 + n] : 0.f;
        w8 = (k0 + 8 < 200 && n < 10) ? W4[(k0 + 8) * 10 + n] : 0.f;
        w9 = (k0 + 9 < 200 && n < 10) ? W4[(k0 + 9) * 10 + n] : 0.f;
    } else {
        const float* W = (which == 2) ? W2 : W3;
        w0 = (k0     < 200 && n < 200) ? W[(k0)     * 200 + n] : 0.f;
        w1 = (k0 + 1 < 200 && n < 200) ? W[(k0 + 1) * 200 + n] : 0.f;
        w8 = (k0 + 8 < 200 && n < 200) ? W[(k0 + 8) * 200 + n] : 0.f;
        w9 = (k0 + 9 < 200 && n < 200) ? W[(k0 + 9) * 200 + n] : 0.f;
    }

    uint32_t b0h, b0l, b1h, b1l;
    split_pack(w0, w1, b0h, b0l);
    split_pack(w8, w9, b1h, b1l);
    dst[loc] = make_uint4(b0h, b1h, b0l, b1l);
}

// ---------------------------------------------------------------------------
// main fused kernel (M = 64 rows per CTA, 3-deep ring, 1 barrier/chunk)
// SMEM (floats):
//   [0,3840)        xs: 3 x [64][20] fp32 x-stage (stride 20)
//   [3840,13824)    ws: 3 x [832] uint4 weight stage
//   [13824,20736)   h_hi: [64][216] bf16 (as 64*108 u32, stride 108 u32)
//   [20736,27648)   h_lo: same
//   [27648,28288)   sb: biases b1[208] b2[208] b3[208] b4[16]
// ---------------------------------------------------------------------------
#define SMEM_BYTES 113152

__global__ void __launch_bounds__(CTA_THREADS, 2)
mlp_kernel(const float* __restrict__ x,
           const float* __restrict__ b1, const float* __restrict__ b2,
           const float* __restrict__ b3, const float* __restrict__ b4,
           float* __restrict__ out) {
    extern __shared__ float smf[];
    float*    xs = smf;                               // 3 x 1280 floats
    uint4*    ws = (uint4*)(smf + 3840);              // 3 x 832 uint4
    uint32_t* hh = (uint32_t*)(smf + 13824);          // 64*108 u32
    uint32_t* hl = (uint32_t*)(smf + 20736);
    float*    sb = smf + 27648;

    const int tid  = threadIdx.x;
    const int lane = tid & 31;
    const int warp = tid >> 5;
    const int g = lane >> 2, t = lane & 3;
    const int mq = warp >> 1;       // M-quarter 0..3 (16 rows each)
    const int nh = warp & 1;        // N-half
    const int r0 = blockIdx.x * 64;

    // biases (padded)
    if (tid < 208) {
        sb[tid]       = (tid < 200) ? b1[tid] : 0.f;
        sb[208 + tid] = (tid < 200) ? b2[tid] : 0.f;
        sb[416 + tid] = (tid < 200) ? b3[tid] : 0.f;
    }
    if (tid < 16) sb[624 + tid] = (tid < 10) ? b4[tid] : 0.f;

    float C[13][4];

    // --------------------- helpers ---------------------
    auto stage_w = [&](const uint4* src, int count, int buf) {
        uint4* d = ws + buf * 832;
        for (int i = tid; i < count; i += CTA_THREADS) cp16(d + i, src + i);
    };
    auto stage_x = [&](int ks, int buf) {
        float* d = xs + buf * 1280;
        int row = tid >> 2, seg = tid & 3;
        cp16(d + row * 20 + seg * 4, x + (size_t)(r0 + row) * 784 + ks * 16 + seg * 4);
    };
    auto zeroC = [&]() {
        #pragma unroll
        for (int j = 0; j < 13; ++j)
            #pragma unroll
            for (int q = 0; q < 4; ++q) C[j][q] = 0.f;
    };
    auto store_h = [&](const float* bias) {
        int row = mq * 16 + g;
        #pragma unroll
        for (int j = 0; j < 13; ++j) {
            int J = 13 * nh + j;
            float2 bb = *(const float2*)(bias + 8 * J + 2 * t);
            float v0 = fmaxf(C[j][0] + bb.x, 0.f);
            float v1 = fmaxf(C[j][1] + bb.y, 0.f);
            float v2 = fmaxf(C[j][2] + bb.x, 0.f);
            float v3 = fmaxf(C[j][3] + bb.y, 0.f);
            uint32_t H, L;
            split_pack(v0, v1, H, L);
            hh[row * 108 + 4 * J + t] = H;
            hl[row * 108 + 4 * J + t] = L;
            split_pack(v2, v3, H, L);
            hh[(row + 8) * 108 + 4 * J + t] = H;
            hl[(row + 8) * 108 + 4 * J + t] = L;
        }
    };
    auto load_a_h = [&](int ks, uint32_t ah[4], uint32_t al[4]) {
        int base = (mq * 16 + g) * 108 + 8 * ks + t;
        ah[0] = hh[base];
        ah[1] = hh[base + 8 * 108];
        ah[2] = hh[base + 4];
        ah[3] = hh[base + 4 + 8 * 108];
        al[0] = hl[base];
        al[1] = hl[base + 8 * 108];
        al[2] = hl[base + 4];
        al[3] = hl[base + 4 + 8 * 108];
    };
    // 39 MMAs, issued term-major within j-groups {5,4,4}:
    // RAW distance between dependent HMMAs = group size (4..5), not 1.
    auto mma_train = [&](const uint4* wb, const uint32_t ah[4], const uint32_t al[4]) {
        {   // group 0: j = 0..4
            uint4 w[5];
            #pragma unroll
            for (int i = 0; i < 5; ++i) w[i] = wb[i * 32];
            #pragma unroll
            for (int i = 0; i < 5; ++i) mma_bf16(C[i], ah, w[i].x, w[i].y);  // hi*hi
            #pragma unroll
            for (int i = 0; i < 5; ++i) mma_bf16(C[i], al, w[i].x, w[i].y);  // lo*hi
            #pragma unroll
            for (int i = 0; i < 5; ++i) mma_bf16(C[i], ah, w[i].z, w[i].w);  // hi*lo
        }
        {   // group 1: j = 5..8
            uint4 w[4];
            #pragma unroll
            for (int i = 0; i < 4; ++i) w[i] = wb[(5 + i) * 32];
            #pragma unroll
            for (int i = 0; i < 4; ++i) mma_bf16(C[5 + i], ah, w[i].x, w[i].y);
            #pragma unroll
            for (int i = 0; i < 4; ++i) mma_bf16(C[5 + i], al, w[i].x, w[i].y);
            #pragma unroll
            for (int i = 0; i < 4; ++i) mma_bf16(C[5 + i], ah, w[i].z, w[i].w);
        }
        {   // group 2: j = 9..12
            uint4 w[4];
            #pragma unroll
            for (int i = 0; i < 4; ++i) w[i] = wb[(9 + i) * 32];
            #pragma unroll
            for (int i = 0; i < 4; ++i) mma_bf16(C[9 + i], ah, w[i].x, w[i].y);
            #pragma unroll
            for (int i = 0; i < 4; ++i) mma_bf16(C[9 + i], al, w[i].x, w[i].y);
            #pragma unroll
            for (int i = 0; i < 4; ++i) mma_bf16(C[9 + i], ah, w[i].z, w[i].w);
        }
    };

    // =========================== Layer 1 (K=784) ===========================
    zeroC();
    stage_x(0, 0); stage_w(g_Wb1, 832, 0); CP_COMMIT;
    stage_x(1, 1); stage_w(g_Wb1 + 832, 832, 1); CP_COMMIT;
    {
        int cur = 0, st = 2;
        for (int ks = 0; ks < NK1; ++ks) {
            CP_WAIT1;                      // group ks complete (ks+1 pending)
            __syncthreads();               // visibility + WAR for buf st
            if (ks + 2 < NK1) { stage_x(ks + 2, st); stage_w(g_Wb1 + (ks + 2) * 832, 832, st); }
            CP_COMMIT;                     // commit every iter (may be empty)

            uint32_t ah[4], al[4];
            {
                const float* xb = xs + cur * 1280 + (mq * 16 + g) * 20;
                float2 p0 = *(const float2*)(xb + 2 * t);
                float2 p1 = *(const float2*)(xb + 160 + 2 * t);        // row+8
                float2 p2 = *(const float2*)(xb + 2 * t + 8);          // k+8
                float2 p3 = *(const float2*)(xb + 160 + 2 * t + 8);
                split_pack(p0.x, p0.y, ah[0], al[0]);
                split_pack(p1.x, p1.y, ah[1], al[1]);
                split_pack(p2.x, p2.y, ah[2], al[2]);
                split_pack(p3.x, p3.y, ah[3], al[3]);
            }
            mma_train(ws + cur * 832 + nh * 13 * 32 + lane, ah, al);
            if (++cur == 3) cur = 0;
            if (++st  == 3) st  = 0;
        }
    }
    __syncthreads();
    store_h(sb);
    __syncthreads();

    // ======================= Layers 2 & 3 (K=208) ==========================
    const uint4* Wmid[2] = { g_Wb2, g_Wb3 };
    for (int l = 0; l < 2; ++l) {
        zeroC();
        stage_w(Wmid[l], 832, 0); CP_COMMIT;
        stage_w(Wmid[l] + 832, 832, 1); CP_COMMIT;
        int cur = 0, st = 2;
        for (int ks = 0; ks < NKH; ++ks) {
            CP_WAIT1;
            __syncthreads();
            if (ks + 2 < NKH) stage_w(Wmid[l] + (ks + 2) * 832, 832, st);
            CP_COMMIT;

            uint32_t ah[4], al[4];
            load_a_h(ks, ah, al);
            mma_train(ws + cur * 832 + nh * 13 * 32 + lane, ah, al);
            if (++cur == 3) cur = 0;
            if (++st  == 3) st  = 0;
        }
        __syncthreads();                 // all h reads done before overwrite
        store_h(sb + 208 * (l + 1));
        __syncthreads();
    }

    // =========================== Layer 4 (N=10) ============================
    float C4[4];
    #pragma unroll
    for (int q = 0; q < 4; ++q) C4[q] = 0.f;

    stage_w(g_Wb4, 64, 0); CP_COMMIT;
    stage_w(g_Wb4 + 64, 64, 1); CP_COMMIT;
    {
        int cur = 0, st = 2;
        for (int ks = 0; ks < NKH; ++ks) {
            CP_WAIT1;
            __syncthreads();
            if (ks + 2 < NKH) stage_w(g_Wb4 + (ks + 2) * 64, 64, st);
            CP_COMMIT;

            uint32_t ah[4], al[4];
            load_a_h(ks, ah, al);
            uint4 w = ws[cur * 832 + nh * 32 + lane];
            mma_bf16(C4, ah, w.x, w.y);
            mma_bf16(C4, al, w.x, w.y);
            mma_bf16(C4, ah, w.z, w.w);
            if (++cur == 3) cur = 0;
            if (++st  == 3) st  = 0;
        }
    }

    // output: cols 0..9 (tile nh*8 + 2t; guard padded cols)
    if (nh == 0 || t == 0) {
        int col = 8 * nh + 2 * t;
        float2 bb = *(const float2*)(sb + 624 + col);
        int rowg = r0 + mq * 16 + g;
        float2 o0 = { C4[0] + bb.x, C4[1] + bb.y };
        float2 o1 = { C4[2] + bb.x, C4[3] + bb.y };
        *(float2*)(out + (size_t)rowg * 10 + col)       = o0;
        *(float2*)(out + (size_t)(rowg + 8) * 10 + col) = o1;
    }
}

// ---------------------------------------------------------------------------
extern "C" void kernel_launch(void* const* d_in, const int* in_sizes, int n_in,
                              void* d_out, int out_size) {
    const float* x  = (const float*)d_in[0];
    const float* cw = (const float*)d_in[1];
    const float* W1 = (const float*)d_in[2];
    const float* b1 = (const float*)d_in[3];
    const float* W2 = (const float*)d_in[4];
    const float* b2 = (const float*)d_in[5];
    const float* W3 = (const float*)d_in[6];
    const float* b3 = (const float*)d_in[7];
    const float* W4 = (const float*)d_in[8];
    const float* b4 = (const float*)d_in[9];
    float* out = (float*)d_out;

    cudaFuncSetAttribute(mlp_kernel, cudaFuncAttributeMaxDynamicSharedMemorySize, SMEM_BYTES);

    prep_kernel<<<247, CTA_THREADS>>>(cw, W1, W2, W3, W4);
    mlp_kernel<<<1024, CTA_THREADS, SMEM_BYTES>>>(x, b1, b2, b3, b4, out);
}

// round 12
// speedup vs baseline: 1.4208x; 1.2198x over previous
#include <cuda_runtime.h>
#include <cuda_bf16.h>
#include <cstdint>

// ============================================================================
// DigitConvolutionalModel: conv folds into W1 -> pure 4-layer MLP
//   784 -> 200 -> 200 -> 200 -> 10, batch 65536, fp32 in/out.
// THIS ROUND: single-pass TF32 (mma.sync.m16n8k8.tf32, fp32 accumulate)
//   replaces bf16x3 -> 26 MMAs/warp/chunk instead of 39 (-33% tensor work),
//   identical memory traffic. Expected rel_err ~3-6e-4 (gate 1e-3).
// Structure = proven best (R7): CTA = 64 rows, 256 threads, warps 4M x 2N,
//   13 j-tiles/warp, 3-deep cp.async ring, one __syncthreads per k-chunk,
//   2 CTAs/SM. Weights pre-folded + tf32-rounded + fragment-linearized.
// ============================================================================

#define CTA_THREADS 256

#define NK1 49
#define NKH 13
#define NJH 26
#define NJO 2

// fragment-linear tf32 weights: uint4 per (ks, j, lane) =
//   {W[k0+t][n], W[k0+t+4][n], W[k0+8+t][n], W[k0+8+t+4][n]}  (tf32 bits)
//   where k0 = 16*ks, n = 8*j + (lane>>2), t = lane&3
__device__ uint4 g_Wb1[NK1 * NJH * 32];
__device__ uint4 g_Wb2[NKH * NJH * 32];
__device__ uint4 g_Wb3[NKH * NJH * 32];
__device__ uint4 g_Wb4[NKH * NJO * 32];

// ---------------------------------------------------------------------------
__device__ __forceinline__ uint32_t to_tf32(float f) {
    uint32_t r;
    asm("cvt.rna.tf32.f32 %0, %1;" : "=r"(r) : "f"(f));
    return r;
}

__device__ __forceinline__ void mma_tf32(float* c,
        uint32_t a0, uint32_t a1, uint32_t a2, uint32_t a3,
        uint32_t b0, uint32_t b1) {
    asm volatile(
        "mma.sync.aligned.m16n8k8.row.col.f32.tf32.tf32.f32 "
        "{%0,%1,%2,%3},{%4,%5,%6,%7},{%8,%9},{%0,%1,%2,%3};"
        : "+f"(c[0]), "+f"(c[1]), "+f"(c[2]), "+f"(c[3])
        : "r"(a0), "r"(a1), "r"(a2), "r"(a3), "r"(b0), "r"(b1));
}

__device__ __forceinline__ void cp16(void* dst_smem, const void* src) {
    uint32_t d = (uint32_t)__cvta_generic_to_shared(dst_smem);
    asm volatile("cp.async.cg.shared.global [%0], [%1], 16;" :: "r"(d), "l"(src));
}
#define CP_COMMIT asm volatile("cp.async.commit_group;" ::: "memory")
#define CP_WAIT1  asm volatile("cp.async.wait_group 1;" ::: "memory")

// ---------------------------------------------------------------------------
// prep kernel: fold conv into W1eff, tf32-round, fragment-linearize
// ---------------------------------------------------------------------------
__device__ __forceinline__ float w_l1(const float* cw, const float* W1, int k, int n) {
    if (n >= 200 || k >= 784) return 0.f;
    int r = k / 28, c = k % 28;
    float s = 0.f;
    #pragma unroll
    for (int dy = 0; dy < 3; ++dy) {
        int i = r - dy;
        if (i < 0 || i > 25) continue;
        #pragma unroll
        for (int dx = 0; dx < 3; ++dx) {
            int j = c - dx;
            if (j < 0 || j > 25) continue;
            s += cw[dy * 3 + dx] * W1[(i * 26 + j) * 200 + n];
        }
    }
    return s;
}

__global__ void prep_kernel(const float* __restrict__ cw,
                            const float* __restrict__ W1,
                            const float* __restrict__ W2,
                            const float* __restrict__ W3,
                            const float* __restrict__ W4) {
    int s = blockIdx.x * CTA_THREADS + threadIdx.x;
    const int E1 = NK1 * NJH * 32;
    const int E2 = E1 + NKH * NJH * 32;
    const int E3 = E2 + NKH * NJH * 32;
    const int E4 = E3 + NKH * NJO * 32;
    if (s >= E4) return;

    uint4* dst; int loc, nj, which;
    if (s < E1)      { dst = g_Wb1; loc = s;      nj = NJH; which = 1; }
    else if (s < E2) { dst = g_Wb2; loc = s - E1; nj = NJH; which = 2; }
    else if (s < E3) { dst = g_Wb3; loc = s - E2; nj = NJH; which = 3; }
    else             { dst = g_Wb4; loc = s - E3; nj = NJO; which = 4; }

    int lane = loc & 31;
    int j    = (loc >> 5) % nj;
    int ks   = loc / (nj * 32);
    int g = lane >> 2, t = lane & 3;
    int n  = 8 * j + g;
    int k0 = 16 * ks;
    int ka = k0 + t, kb = k0 + t + 4, kc = k0 + 8 + t, kd = k0 + 12 + t;

    float w0, w1, w2, w3;
    if (which == 1) {
        w0 = w_l1(cw, W1, ka, n);
        w1 = w_l1(cw, W1, kb, n);
        w2 = w_l1(cw, W1, kc, n);
        w3 = w_l1(cw, W1, kd, n);
    } else if (which == 4) {
        w0 = (ka < 200 && n < 10) ? W4[ka * 10 + n] : 0.f;
        w1 = (kb < 200 && n < 10) ? W4[kb * 10 + n] : 0.f;
        w2 = (kc < 200 && n < 10) ? W4[kc * 10 + n] : 0.f;
        w3 = (kd < 200 && n < 10) ? W4[kd * 10 + n] : 0.f;
    } else {
        const float* W = (which == 2) ? W2 : W3;
        w0 = (ka < 200 && n < 200) ? W[ka * 200 + n] : 0.f;
        w1 = (kb < 200 && n < 200) ? W[kb * 200 + n] : 0.f;
        w2 = (kc < 200 && n < 200) ? W[kc * 200 + n] : 0.f;
        w3 = (kd < 200 && n < 200) ? W[kd * 200 + n] : 0.f;
    }

    dst[loc] = make_uint4(to_tf32(w0), to_tf32(w1), to_tf32(w2), to_tf32(w3));
}

// ---------------------------------------------------------------------------
// main fused kernel (M = 64 rows per CTA, 3-deep ring, 1 barrier/chunk)
// SMEM (floats):
//   [0,3840)        xs: 3 x [64][20] fp32 x-stage (stride 20)
//   [3840,13824)    ws: 3 x [832] uint4 weight stage
//   [13824,27392)   hf: [64][212] tf32-rounded fp32 h (stride 212)
//   [27392,28032)   sb: biases b1[208] b2[208] b3[208] b4[16]
// ---------------------------------------------------------------------------
#define SMEM_BYTES 112128
#define HSTR 212

__global__ void __launch_bounds__(CTA_THREADS, 2)
mlp_kernel(const float* __restrict__ x,
           const float* __restrict__ b1, const float* __restrict__ b2,
           const float* __restrict__ b3, const float* __restrict__ b4,
           float* __restrict__ out) {
    extern __shared__ float smf[];
    float*    xs = smf;                               // 3 x 1280 floats
    uint4*    ws = (uint4*)(smf + 3840);              // 3 x 832 uint4
    uint32_t* hf = (uint32_t*)(smf + 13824);          // 64 x 212 tf32 bits
    float*    sb = smf + 27392;

    const int tid  = threadIdx.x;
    const int lane = tid & 31;
    const int warp = tid >> 5;
    const int g = lane >> 2, t = lane & 3;
    const int mq = warp >> 1;       // M-quarter 0..3 (16 rows each)
    const int nh = warp & 1;        // N-half
    const int r0 = blockIdx.x * 64;

    // biases (padded)
    if (tid < 208) {
        sb[tid]       = (tid < 200) ? b1[tid] : 0.f;
        sb[208 + tid] = (tid < 200) ? b2[tid] : 0.f;
        sb[416 + tid] = (tid < 200) ? b3[tid] : 0.f;
    }
    if (tid < 16) sb[624 + tid] = (tid < 10) ? b4[tid] : 0.f;

    float C[13][4];

    // --------------------- helpers ---------------------
    auto stage_w = [&](const uint4* src, int count, int buf) {
        uint4* d = ws + buf * 832;
        for (int i = tid; i < count; i += CTA_THREADS) cp16(d + i, src + i);
    };
    auto stage_x = [&](int ks, int buf) {
        float* d = xs + buf * 1280;
        int row = tid >> 2, seg = tid & 3;
        cp16(d + row * 20 + seg * 4, x + (size_t)(r0 + row) * 784 + ks * 16 + seg * 4);
    };
    auto zeroC = [&]() {
        #pragma unroll
        for (int j = 0; j < 13; ++j)
            #pragma unroll
            for (int q = 0; q < 4; ++q) C[j][q] = 0.f;
    };
    // h producer: tf32-rounded fp32, row-major stride 212
    auto store_h = [&](const float* bias) {
        int row = mq * 16 + g;
        #pragma unroll
        for (int j = 0; j < 13; ++j) {
            int J = 13 * nh + j;
            float2 bb = *(const float2*)(bias + 8 * J + 2 * t);
            float v0 = fmaxf(C[j][0] + bb.x, 0.f);
            float v1 = fmaxf(C[j][1] + bb.y, 0.f);
            float v2 = fmaxf(C[j][2] + bb.x, 0.f);
            float v3 = fmaxf(C[j][3] + bb.y, 0.f);
            uint2 u0 = make_uint2(to_tf32(v0), to_tf32(v1));
            uint2 u1 = make_uint2(to_tf32(v2), to_tf32(v3));
            *(uint2*)(hf + row * HSTR + 8 * J + 2 * t)       = u0;
            *(uint2*)(hf + (row + 8) * HSTR + 8 * J + 2 * t) = u1;
        }
    };
    // consumer: direct tf32 A-fragment loads (conflict-free LDS.32)
    auto load_a_h = [&](int ks, uint32_t a[8]) {
        int base = (mq * 16 + g) * HSTR + 16 * ks + t;
        a[0] = hf[base];
        a[1] = hf[base + 8 * HSTR];
        a[2] = hf[base + 4];
        a[3] = hf[base + 4 + 8 * HSTR];
        a[4] = hf[base + 8];
        a[5] = hf[base + 8 + 8 * HSTR];
        a[6] = hf[base + 12];
        a[7] = hf[base + 12 + 8 * HSTR];
    };
    // 26 MMAs (13 j x 2 k8-steps), grouped {5,4,4}, step-major in group
    auto mma_train = [&](const uint4* wb, const uint32_t a[8]) {
        {   // j = 0..4
            uint4 w[5];
            #pragma unroll
            for (int i = 0; i < 5; ++i) w[i] = wb[i * 32];
            #pragma unroll
            for (int i = 0; i < 5; ++i) mma_tf32(C[i], a[0], a[1], a[2], a[3], w[i].x, w[i].y);
            #pragma unroll
            for (int i = 0; i < 5; ++i) mma_tf32(C[i], a[4], a[5], a[6], a[7], w[i].z, w[i].w);
        }
        {   // j = 5..8
            uint4 w[4];
            #pragma unroll
            for (int i = 0; i < 4; ++i) w[i] = wb[(5 + i) * 32];
            #pragma unroll
            for (int i = 0; i < 4; ++i) mma_tf32(C[5 + i], a[0], a[1], a[2], a[3], w[i].x, w[i].y);
            #pragma unroll
            for (int i = 0; i < 4; ++i) mma_tf32(C[5 + i], a[4], a[5], a[6], a[7], w[i].z, w[i].w);
        }
        {   // j = 9..12
            uint4 w[4];
            #pragma unroll
            for (int i = 0; i < 4; ++i) w[i] = wb[(9 + i) * 32];
            #pragma unroll
            for (int i = 0; i < 4; ++i) mma_tf32(C[9 + i], a[0], a[1], a[2], a[3], w[i].x, w[i].y);
            #pragma unroll
            for (int i = 0; i < 4; ++i) mma_tf32(C[9 + i], a[4], a[5], a[6], a[7], w[i].z, w[i].w);
        }
    };

    // =========================== Layer 1 (K=784) ===========================
    zeroC();
    stage_x(0, 0); stage_w(g_Wb1, 832, 0); CP_COMMIT;
    stage_x(1, 1); stage_w(g_Wb1 + 832, 832, 1); CP_COMMIT;
    {
        int cur = 0, st = 2;
        for (int ks = 0; ks < NK1; ++ks) {
            CP_WAIT1;                      // group ks complete (ks+1 pending)
            __syncthreads();               // visibility + WAR for buf st
            if (ks + 2 < NK1) { stage_x(ks + 2, st); stage_w(g_Wb1 + (ks + 2) * 832, 832, st); }
            CP_COMMIT;

            uint32_t a[8];
            {
                const float* xb = xs + cur * 1280 + (mq * 16 + g) * 20;
                a[0] = to_tf32(xb[t]);
                a[1] = to_tf32(xb[160 + t]);          // row+8
                a[2] = to_tf32(xb[t + 4]);
                a[3] = to_tf32(xb[160 + t + 4]);
                a[4] = to_tf32(xb[t + 8]);
                a[5] = to_tf32(xb[160 + t + 8]);
                a[6] = to_tf32(xb[t + 12]);
                a[7] = to_tf32(xb[160 + t + 12]);
            }
            mma_train(ws + cur * 832 + nh * 13 * 32 + lane, a);
            if (++cur == 3) cur = 0;
            if (++st  == 3) st  = 0;
        }
    }
    __syncthreads();
    store_h(sb);
    __syncthreads();

    // ======================= Layers 2 & 3 (K=208) ==========================
    const uint4* Wmid[2] = { g_Wb2, g_Wb3 };
    for (int l = 0; l < 2; ++l) {
        zeroC();
        stage_w(Wmid[l], 832, 0); CP_COMMIT;
        stage_w(Wmid[l] + 832, 832, 1); CP_COMMIT;
        int cur = 0, st = 2;
        for (int ks = 0; ks < NKH; ++ks) {
            CP_WAIT1;
            __syncthreads();
            if (ks + 2 < NKH) stage_w(Wmid[l] + (ks + 2) * 832, 832, st);
            CP_COMMIT;

            uint32_t a[8];
            load_a_h(ks, a);
            mma_train(ws + cur * 832 + nh * 13 * 32 + lane, a);
            if (++cur == 3) cur = 0;
            if (++st  == 3) st  = 0;
        }
        __syncthreads();                 // all h reads done before overwrite
        store_h(sb + 208 * (l + 1));
        __syncthreads();
    }

    // =========================== Layer 4 (N=10) ============================
    float C4[4];
    #pragma unroll
    for (int q = 0; q < 4; ++q) C4[q] = 0.f;

    stage_w(g_Wb4, 64, 0); CP_COMMIT;
    stage_w(g_Wb4 + 64, 64, 1); CP_COMMIT;
    {
        int cur = 0, st = 2;
        for (int ks = 0; ks < NKH; ++ks) {
            CP_WAIT1;
            __syncthreads();
            if (ks + 2 < NKH) stage_w(g_Wb4 + (ks + 2) * 64, 64, st);
            CP_COMMIT;

            uint32_t a[8];
            load_a_h(ks, a);
            uint4 w = ws[cur * 832 + nh * 32 + lane];
            mma_tf32(C4, a[0], a[1], a[2], a[3], w.x, w.y);
            mma_tf32(C4, a[4], a[5], a[6], a[7], w.z, w.w);
            if (++cur == 3) cur = 0;
            if (++st  == 3) st  = 0;
        }
    }

    // output: cols 0..9 (tile nh*8 + 2t; guard padded cols)
    if (nh == 0 || t == 0) {
        int col = 8 * nh + 2 * t;
        float2 bb = *(const float2*)(sb + 624 + col);
        int rowg = r0 + mq * 16 + g;
        float2 o0 = { C4[0] + bb.x, C4[1] + bb.y };
        float2 o1 = { C4[2] + bb.x, C4[3] + bb.y };
        *(float2*)(out + (size_t)rowg * 10 + col)       = o0;
        *(float2*)(out + (size_t)(rowg + 8) * 10 + col) = o1;
    }
}

// ---------------------------------------------------------------------------
extern "C" void kernel_launch(void* const* d_in, const int* in_sizes, int n_in,
                              void* d_out, int out_size) {
    const float* x  = (const float*)d_in[0];
    const float* cw = (const float*)d_in[1];
    const float* W1 = (const float*)d_in[2];
    const float* b1 = (const float*)d_in[3];
    const float* W2 = (const float*)d_in[4];
    const float* b2 = (const float*)d_in[5];
    const float* W3 = (const float*)d_in[6];
    const float* b3 = (const float*)d_in[7];
    const float* W4 = (const float*)d_in[8];
    const float* b4 = (const float*)d_in[9];
    float* out = (float*)d_out;

    cudaFuncSetAttribute(mlp_kernel, cudaFuncAttributeMaxDynamicSharedMemorySize, SMEM_BYTES);

    prep_kernel<<<247, CTA_THREADS>>>(cw, W1, W2, W3, W4);
    mlp_kernel<<<1024, CTA_THREADS, SMEM_BYTES>>>(x, b1, b2, b3, b4, out);
}